// round 7
// baseline (speedup 1.0000x reference)
#include <cuda_runtime.h>
#include <cstdint>
#include <cstddef>

// FPS: B=8, N=131072, NPOINT=1024 -> out [8,1024,3] fp32.
// R3 skeleton: 8 clusters (one per batch) x 8 CTAs x 512 threads.
// 16 pairs/thread: pairs 0..11 in REGISTERS, pairs 12..15 streamed from SMEM
// via LDS.128 (thread-major layout). Pair-major SMEM mirror kept for the reg
// pairs so any thread's winning candidate coords can be fetched. Argmax =
// (max dist, min index) via REDUX; winner coords ride warpred -> DSMEM slots;
// one barrier.cluster per step; every warp reduces the 8 slots locally.

#define NB       8
#define NPTS     131072
#define NSAMP    1024
#define CSIZE    8
#define TPB      512
#define PPB      (NPTS / CSIZE)    // 16384 points per CTA
#define PAIRS    (PPB / 2)         // 8192 pairs per CTA
#define TOTJ     (PAIRS / TPB)     // 16 pairs per thread
#define REGJ     12                // pairs per thread held in registers
#define STRJ     (TOTJ - REGJ)     // 4 pairs streamed from SMEM
#define NPT      (2 * TOTJ)        // 32 points per thread
#define NWARPS   (TPB / 32)        // 16
#define APAIRS   (REGJ * TPB)      // 6144 pairs in region A (pair-major)
#define BPAIRS   (STRJ * TPB)      // 2048 pairs in region B (thread-major)

struct __align__(16) Red { unsigned v, i; float x, y, z; unsigned pad[3]; };  // 32B

struct Smem {
    Red warpred[NWARPS];                    // 512 B
    Red slots[2][CSIZE];                    // 512 B
    unsigned long long xa[APAIRS];          // region A: pair-major (mirror of reg pairs)
    unsigned long long ya[APAIRS];
    unsigned long long za[APAIRS];
    unsigned long long xb[BPAIRS];          // region B: thread-major [tid*STRJ + jj]
    unsigned long long yb[BPAIRS];
    unsigned long long zb[BPAIRS];
};

// ---------- asm helpers ----------
__device__ __forceinline__ unsigned ctarank() {
    unsigned r; asm("mov.u32 %0, %%cluster_ctarank;" : "=r"(r)); return r;
}
__device__ __forceinline__ unsigned cvta_s(const void* p) {
    unsigned r;
    asm("{ .reg .u64 t; cvta.to.shared.u64 t, %1; cvt.u32.u64 %0, t; }"
        : "=r"(r) : "l"(p));
    return r;
}
__device__ __forceinline__ unsigned mapa_s(unsigned laddr, unsigned rank) {
    unsigned r;
    asm("mapa.shared::cluster.u32 %0, %1, %2;" : "=r"(r) : "r"(laddr), "r"(rank));
    return r;
}
__device__ __forceinline__ unsigned long long packf2(float lo, float hi) {
    unsigned long long r;
    asm("mov.b64 %0, {%1, %2};" : "=l"(r) : "f"(lo), "f"(hi));
    return r;
}
__device__ __forceinline__ void unpackf2(unsigned long long v, float& lo, float& hi) {
    asm("mov.b64 {%0, %1}, %2;" : "=f"(lo), "=f"(hi) : "l"(v));
}
__device__ __forceinline__ unsigned long long addx2(unsigned long long a,
                                                    unsigned long long b) {
    unsigned long long r;
    asm("add.rn.f32x2 %0, %1, %2;" : "=l"(r) : "l"(a), "l"(b));
    return r;
}
__device__ __forceinline__ unsigned long long mulx2(unsigned long long a,
                                                    unsigned long long b) {
    unsigned long long r;
    asm("mul.rn.f32x2 %0, %1, %2;" : "=l"(r) : "l"(a), "l"(b));
    return r;
}
__device__ __forceinline__ unsigned long long fmx2(unsigned long long a,
                                                   unsigned long long b,
                                                   unsigned long long c) {
    unsigned long long r;
    asm("fma.rn.f32x2 %0, %1, %2, %3;" : "=l"(r) : "l"(a), "l"(b), "l"(c));
    return r;
}
__device__ __forceinline__ void st_cluster_v4(unsigned raddr, unsigned a, unsigned b,
                                              unsigned c, unsigned d) {
    asm volatile("st.shared::cluster.v4.b32 [%0], {%1,%2,%3,%4};"
                 :: "r"(raddr), "r"(a), "r"(b), "r"(c), "r"(d) : "memory");
}
__device__ __forceinline__ void st_cluster_u32(unsigned raddr, unsigned v) {
    asm volatile("st.shared::cluster.u32 [%0], %1;" :: "r"(raddr), "r"(v) : "memory");
}
__device__ __forceinline__ void cluster_bar() {
    asm volatile("barrier.cluster.arrive.aligned;" ::: "memory");
    asm volatile("barrier.cluster.wait.aligned;"   ::: "memory");
}

__global__ void __launch_bounds__(TPB, 1)
fps_kernel(const float* __restrict__ xyz, float* __restrict__ out) {
    extern __shared__ __align__(16) unsigned char smem_raw[];
    Smem* s = reinterpret_cast<Smem*>(smem_raw);

    const int      tid  = threadIdx.x;
    const unsigned lane = tid & 31;
    const unsigned warp = (unsigned)tid >> 5;
    const unsigned rank = ctarank();
    const int      batch = blockIdx.x / CSIZE;

    const float* __restrict__ base = xyz + (size_t)batch * NPTS * 3;
    const unsigned pbase = rank * PPB;

    // ---- load: reg pairs -> registers + pair-major mirror; streamed -> thread-major
    unsigned long long X[REGJ], Y[REGJ], Z[REGJ];
#pragma unroll
    for (int j = 0; j < TOTJ; ++j) {
        unsigned P = (unsigned)j * TPB + (unsigned)tid;   // global pair id in CTA
        const float2* p = reinterpret_cast<const float2*>(
            base + (size_t)(pbase + 2u * P) * 3);
        float2 a = p[0];  // x0 y0
        float2 b = p[1];  // z0 x1
        float2 c = p[2];  // y1 z1
        unsigned long long px = packf2(a.x, b.y);
        unsigned long long py = packf2(a.y, c.x);
        unsigned long long pz = packf2(b.x, c.y);
        if (j < REGJ) {
            X[j] = px; Y[j] = py; Z[j] = pz;
            s->xa[P] = px; s->ya[P] = py; s->za[P] = pz;
        } else {
            unsigned q = (unsigned)tid * STRJ + (unsigned)(j - REGJ);
            s->xb[q] = px; s->yb[q] = py; s->zb[q] = pz;
        }
    }

    float m[NPT];
#pragma unroll
    for (int k = 0; k < NPT; ++k) m[k] = __int_as_float(0x7f800000);  // +inf

    // remote slot addresses for pushes (warp0 lanes < CSIZE), both parities
    unsigned rs0 = 0, rs1 = 0;
    if (warp == 0 && lane < CSIZE) {
        rs0 = mapa_s(cvta_s(&s->slots[0][rank]), lane);
        rs1 = mapa_s(cvta_s(&s->slots[1][rank]), lane);
    }

    // initial centroid = point 0 of this batch
    float cx = __ldg(base + 0);
    float cy = __ldg(base + 1);
    float cz = __ldg(base + 2);
    if (rank == 0 && tid == 0) {
        float* o = out + (size_t)batch * NSAMP * 3;
        o[0] = cx; o[1] = cy; o[2] = cz;
    }
    __syncthreads();   // smem ready

    const ulonglong2* xb2 =
        reinterpret_cast<const ulonglong2*>(&s->xb[(unsigned)tid * STRJ]);
    const ulonglong2* yb2 =
        reinterpret_cast<const ulonglong2*>(&s->yb[(unsigned)tid * STRJ]);
    const ulonglong2* zb2 =
        reinterpret_cast<const ulonglong2*>(&s->zb[(unsigned)tid * STRJ]);

    for (int t = 1; t < NSAMP; ++t) {
        const unsigned long long ncx = packf2(-cx, -cx);
        const unsigned long long ncy = packf2(-cy, -cy);
        const unsigned long long ncz = packf2(-cz, -cz);

        float bmA = -1.0f, bmB = -1.0f;

        // ---- register pairs (no LDS) ----
#pragma unroll
        for (int j = 0; j < REGJ; ++j) {
            unsigned long long dx = addx2(X[j], ncx);
            unsigned long long dy = addx2(Y[j], ncy);
            unsigned long long dz = addx2(Z[j], ncz);
            unsigned long long dd = mulx2(dx, dx);
            dd = fmx2(dy, dy, dd);
            dd = fmx2(dz, dz, dd);
            float d0, d1; unpackf2(dd, d0, d1);
            float m0 = fminf(m[2 * j],     d0);
            float m1 = fminf(m[2 * j + 1], d1);
            m[2 * j] = m0; m[2 * j + 1] = m1;
            bmA = fmaxf(bmA, m0);
            bmB = fmaxf(bmB, m1);
        }
        // ---- streamed pairs: LDS.128, 2 pairs per load ----
#pragma unroll
        for (int h = 0; h < STRJ / 2; ++h) {
            ulonglong2 xv = xb2[h];
            ulonglong2 yv = yb2[h];
            ulonglong2 zv = zb2[h];
#pragma unroll
            for (int e = 0; e < 2; ++e) {
                int j = REGJ + 2 * h + e;
                unsigned long long dx = addx2(e ? xv.y : xv.x, ncx);
                unsigned long long dy = addx2(e ? yv.y : yv.x, ncy);
                unsigned long long dz = addx2(e ? zv.y : zv.x, ncz);
                unsigned long long dd = mulx2(dx, dx);
                dd = fmx2(dy, dy, dd);
                dd = fmx2(dz, dz, dd);
                float d0, d1; unpackf2(dd, d0, d1);
                float m0 = fminf(m[2 * j],     d0);
                float m1 = fminf(m[2 * j + 1], d1);
                m[2 * j] = m0; m[2 * j + 1] = m1;
                bmA = fmaxf(bmA, m0);
                bmB = fmaxf(bmB, m1);
            }
        }
        const float bm = fmaxf(bmA, bmB);

        // ---- smallest k with m[k]==bm (downward scan) ----
        int kk = 0;
#pragma unroll
        for (int k = NPT - 1; k >= 0; --k)
            if (m[k] == bm) kk = k;

        const unsigned jw   = (unsigned)kk >> 1;
        const unsigned Pw   = jw * TPB + (unsigned)tid;
        const unsigned gidx = pbase + 2u * Pw + (unsigned)(kk & 1);

        unsigned long long wx, wy, wz;
        if (jw < REGJ) {
            wx = s->xa[Pw]; wy = s->ya[Pw]; wz = s->za[Pw];
        } else {
            unsigned q = (unsigned)tid * STRJ + (jw - REGJ);
            wx = s->xb[q]; wy = s->yb[q]; wz = s->zb[q];
        }
        float a0, a1, b0, b1, c0, c1;
        unpackf2(wx, a0, a1);
        unpackf2(wy, b0, b1);
        unpackf2(wz, c0, c1);
        float candx = (kk & 1) ? a1 : a0;
        float candy = (kk & 1) ? b1 : b0;
        float candz = (kk & 1) ? c1 : c0;

        // ---- warp reduce: max dist bits, then min index among maxima ----
        unsigned vb = __float_as_uint(bm);   // d>=0: int order == float order
        unsigned wv = __reduce_max_sync(0xffffffffu, vb);
        unsigned cd = (vb == wv) ? gidx : 0xffffffffu;
        unsigned wi = __reduce_min_sync(0xffffffffu, cd);
        if (cd == wi) {                      // unique winner lane stores
            *reinterpret_cast<uint4*>(&s->warpred[warp]) =
                make_uint4(wv, wi, __float_as_uint(candx), __float_as_uint(candy));
            s->warpred[warp].z = candz;
        }
        __syncthreads();

        const int par = t & 1;

        // ---- block reduce over 16 warp partials + push to all 8 peers ----
        if (warp == 0) {
            unsigned v = 0, i = 0xffffffffu, xw = 0, yw = 0, zw = 0;
            if (lane < NWARPS) {
                uint4 w = *reinterpret_cast<const uint4*>(&s->warpred[lane]);
                v = w.x; i = w.y; xw = w.z; yw = w.w;
                zw = __float_as_uint(s->warpred[lane].z);
            }
            unsigned bv = __reduce_max_sync(0xffffffffu, v);
            unsigned bc = (v == bv) ? i : 0xffffffffu;
            unsigned bi = __reduce_min_sync(0xffffffffu, bc);
            unsigned msk = __ballot_sync(0xffffffffu, bc == bi);
            int L = __ffs(msk) - 1;
            xw = __shfl_sync(0xffffffffu, xw, L);
            yw = __shfl_sync(0xffffffffu, yw, L);
            zw = __shfl_sync(0xffffffffu, zw, L);
            if (lane < CSIZE) {
                unsigned ra = par ? rs1 : rs0;
                st_cluster_v4(ra, bv, bi, xw, yw);
                st_cluster_u32(ra + 16, zw);
            }
        }

        // one cluster barrier per step (arrive releases the DSMEM stores)
        cluster_bar();

        // ---- EVERY warp reduces the 8 slots -> next centroid in registers ----
        {
            unsigned v = 0, i = 0xffffffffu, xw = 0, yw = 0, zw = 0;
            if (lane < CSIZE) {
                uint4 w = *reinterpret_cast<const uint4*>(&s->slots[par][lane]);
                v = w.x; i = w.y; xw = w.z; yw = w.w;
                zw = __float_as_uint(s->slots[par][lane].z);
            }
            unsigned cv = __reduce_max_sync(0xffffffffu, v);
            unsigned cc = (v == cv) ? i : 0xffffffffu;
            unsigned ci = __reduce_min_sync(0xffffffffu, cc);
            unsigned msk = __ballot_sync(0xffffffffu, cc == ci);
            int W = __ffs(msk) - 1;
            cx = __uint_as_float(__shfl_sync(0xffffffffu, xw, W));
            cy = __uint_as_float(__shfl_sync(0xffffffffu, yw, W));
            cz = __uint_as_float(__shfl_sync(0xffffffffu, zw, W));
            if (rank == 0 && tid == 0) {
                float* o = out + ((size_t)batch * NSAMP + (size_t)t) * 3;
                o[0] = cx; o[1] = cy; o[2] = cz;
            }
        }
        // warpred: each warp rewrites only its own entry after its own warp
        // stage; warp0 reads right after the block-wide __syncthreads.
        // slots: double-buffered by parity, protected by the cluster barrier.
    }

    cluster_bar();  // keep CTAs alive until all DSMEM traffic has landed
}

extern "C" void kernel_launch(void* const* d_in, const int* in_sizes, int n_in,
                              void* d_out, int out_size) {
    (void)in_sizes; (void)n_in; (void)out_size;
    const float* xyz = (const float*)d_in[0];
    float* out = (float*)d_out;

    cudaFuncSetAttribute(fps_kernel,
                         cudaFuncAttributeMaxDynamicSharedMemorySize,
                         (int)sizeof(Smem));

    cudaLaunchConfig_t cfg = {};
    cfg.gridDim  = dim3(NB * CSIZE, 1, 1);   // 64 CTAs
    cfg.blockDim = dim3(TPB, 1, 1);
    cfg.dynamicSmemBytes = sizeof(Smem);
    cfg.stream = 0;

    cudaLaunchAttribute attr[1];
    attr[0].id = cudaLaunchAttributeClusterDimension;
    attr[0].val.clusterDim.x = CSIZE;
    attr[0].val.clusterDim.y = 1;
    attr[0].val.clusterDim.z = 1;
    cfg.attrs = attr;
    cfg.numAttrs = 1;

    cudaLaunchKernelEx(&cfg, fps_kernel, xyz, out);
}

// round 8
// speedup vs baseline: 1.0541x; 1.0541x over previous
#include <cuda_runtime.h>
#include <cstdint>
#include <cstddef>

// FPS: B=8, N=131072, NPOINT=1024 -> out [8,1024,3] fp32.
// R3 skeleton: 8 clusters (one per batch) x 8 CTAs x 512 threads.
// 16 pairs/thread: pairs 0..7 in REGISTERS (pair-major SMEM mirror for the
// once-per-step candidate fetch), pairs 8..15 streamed from SMEM via
// conflict-free chunked thread-major LDS.128. All distance math forced to
// FFMA2 via fma.rn.f32x2 (sub as fma(x,1,-c), square as fma(d,d,+0)) --
// bit-exact. Argmax = (max dist, min index) via REDUX; winner coords ride
// warpred -> DSMEM slots; one barrier.cluster per step; every warp reduces
// the 8 slots locally so the next centroid lands in registers.

#define NB       8
#define NPTS     131072
#define NSAMP    1024
#define CSIZE    8
#define TPB      512
#define PPB      (NPTS / CSIZE)    // 16384 points per CTA
#define PAIRS    (PPB / 2)         // 8192 pairs per CTA
#define TOTJ     (PAIRS / TPB)     // 16 pairs per thread
#define REGJ     8                 // pairs per thread held in registers
#define STRJ     (TOTJ - REGJ)     // 8 pairs streamed from SMEM
#define NCHUNK   (STRJ / 2)        // 4 chunks of 2 pairs
#define NPT      (2 * TOTJ)        // 32 points per thread
#define NWARPS   (TPB / 32)        // 16
#define APAIRS   (REGJ * TPB)      // 4096 pairs, pair-major mirror

struct __align__(16) Red { unsigned v, i; float x, y, z; unsigned pad[3]; };  // 32B

struct Smem {
    Red warpred[NWARPS];                       // 512 B
    Red slots[2][CSIZE];                       // 512 B
    unsigned long long xa[APAIRS];             // mirror of register pairs (pair-major)
    unsigned long long ya[APAIRS];
    unsigned long long za[APAIRS];
    ulonglong2 xb2[NCHUNK][TPB];               // streamed pairs, chunked thread-major
    ulonglong2 yb2[NCHUNK][TPB];               // [h][tid] -> pairs j=8+2h (.x), 9+2h (.y)
    ulonglong2 zb2[NCHUNK][TPB];
};

// ---------- asm helpers ----------
__device__ __forceinline__ unsigned ctarank() {
    unsigned r; asm("mov.u32 %0, %%cluster_ctarank;" : "=r"(r)); return r;
}
__device__ __forceinline__ unsigned cvta_s(const void* p) {
    unsigned r;
    asm("{ .reg .u64 t; cvta.to.shared.u64 t, %1; cvt.u32.u64 %0, t; }"
        : "=r"(r) : "l"(p));
    return r;
}
__device__ __forceinline__ unsigned mapa_s(unsigned laddr, unsigned rank) {
    unsigned r;
    asm("mapa.shared::cluster.u32 %0, %1, %2;" : "=r"(r) : "r"(laddr), "r"(rank));
    return r;
}
__device__ __forceinline__ unsigned long long packf2(float lo, float hi) {
    unsigned long long r;
    asm("mov.b64 %0, {%1, %2};" : "=l"(r) : "f"(lo), "f"(hi));
    return r;
}
__device__ __forceinline__ void unpackf2(unsigned long long v, float& lo, float& hi) {
    asm("mov.b64 {%0, %1}, %2;" : "=f"(lo), "=f"(hi) : "l"(v));
}
__device__ __forceinline__ unsigned long long fmx2(unsigned long long a,
                                                   unsigned long long b,
                                                   unsigned long long c) {
    unsigned long long r;
    asm("fma.rn.f32x2 %0, %1, %2, %3;" : "=l"(r) : "l"(a), "l"(b), "l"(c));
    return r;
}
__device__ __forceinline__ void st_cluster_v4(unsigned raddr, unsigned a, unsigned b,
                                              unsigned c, unsigned d) {
    asm volatile("st.shared::cluster.v4.b32 [%0], {%1,%2,%3,%4};"
                 :: "r"(raddr), "r"(a), "r"(b), "r"(c), "r"(d) : "memory");
}
__device__ __forceinline__ void st_cluster_u32(unsigned raddr, unsigned v) {
    asm volatile("st.shared::cluster.u32 [%0], %1;" :: "r"(raddr), "r"(v) : "memory");
}
__device__ __forceinline__ void cluster_bar() {
    asm volatile("barrier.cluster.arrive.aligned;" ::: "memory");
    asm volatile("barrier.cluster.wait.aligned;"   ::: "memory");
}

__global__ void __launch_bounds__(TPB, 1)
fps_kernel(const float* __restrict__ xyz, float* __restrict__ out) {
    extern __shared__ __align__(16) unsigned char smem_raw[];
    Smem* s = reinterpret_cast<Smem*>(smem_raw);

    const int      tid  = threadIdx.x;
    const unsigned lane = tid & 31;
    const unsigned warp = (unsigned)tid >> 5;
    const unsigned rank = ctarank();
    const int      batch = blockIdx.x / CSIZE;

    const float* __restrict__ base = xyz + (size_t)batch * NPTS * 3;
    const unsigned pbase = rank * PPB;

    // ---- load: reg pairs -> registers + pair-major mirror; streamed -> chunks
    unsigned long long X[REGJ], Y[REGJ], Z[REGJ];
#pragma unroll
    for (int j = 0; j < TOTJ; ++j) {
        unsigned P = (unsigned)j * TPB + (unsigned)tid;   // global pair id in CTA
        const float2* p = reinterpret_cast<const float2*>(
            base + (size_t)(pbase + 2u * P) * 3);
        float2 a = p[0];  // x0 y0
        float2 b = p[1];  // z0 x1
        float2 c = p[2];  // y1 z1
        unsigned long long px = packf2(a.x, b.y);
        unsigned long long py = packf2(a.y, c.x);
        unsigned long long pz = packf2(b.x, c.y);
        if (j < REGJ) {
            X[j] = px; Y[j] = py; Z[j] = pz;
            s->xa[P] = px; s->ya[P] = py; s->za[P] = pz;
        } else {
            int h = (j - REGJ) >> 1;
            if ((j - REGJ) & 1) {
                s->xb2[h][tid].y = px; s->yb2[h][tid].y = py; s->zb2[h][tid].y = pz;
            } else {
                s->xb2[h][tid].x = px; s->yb2[h][tid].x = py; s->zb2[h][tid].x = pz;
            }
        }
    }

    float m[NPT];
#pragma unroll
    for (int k = 0; k < NPT; ++k) m[k] = __int_as_float(0x7f800000);  // +inf

    // remote slot addresses for pushes (warp0 lanes < CSIZE), both parities
    unsigned rs0 = 0, rs1 = 0;
    if (warp == 0 && lane < CSIZE) {
        rs0 = mapa_s(cvta_s(&s->slots[0][rank]), lane);
        rs1 = mapa_s(cvta_s(&s->slots[1][rank]), lane);
    }

    // initial centroid = point 0 of this batch
    float cx = __ldg(base + 0);
    float cy = __ldg(base + 1);
    float cz = __ldg(base + 2);
    if (rank == 0 && tid == 0) {
        float* o = out + (size_t)batch * NSAMP * 3;
        o[0] = cx; o[1] = cy; o[2] = cz;
    }
    __syncthreads();   // smem ready

    const unsigned long long ONE2  = packf2(1.0f, 1.0f);
    const unsigned long long ZERO2 = 0ULL;   // packed {+0,+0}

    for (int t = 1; t < NSAMP; ++t) {
        const unsigned long long ncx = packf2(-cx, -cx);
        const unsigned long long ncy = packf2(-cy, -cy);
        const unsigned long long ncz = packf2(-cz, -cz);

        float bmA = -1.0f, bmB = -1.0f;

        // ---- register pairs: 6 FFMA2 + 2 min + 2 max per pair ----
#pragma unroll
        for (int j = 0; j < REGJ; ++j) {
            unsigned long long dx = fmx2(X[j], ONE2, ncx);   // x - cx (exact)
            unsigned long long dy = fmx2(Y[j], ONE2, ncy);
            unsigned long long dz = fmx2(Z[j], ONE2, ncz);
            unsigned long long dd = fmx2(dx, dx, ZERO2);     // dx*dx (exact)
            dd = fmx2(dy, dy, dd);
            dd = fmx2(dz, dz, dd);
            float d0, d1; unpackf2(dd, d0, d1);
            float m0 = fminf(m[2 * j],     d0);
            float m1 = fminf(m[2 * j + 1], d1);
            m[2 * j] = m0; m[2 * j + 1] = m1;
            bmA = fmaxf(bmA, m0);
            bmB = fmaxf(bmB, m1);
        }
        // ---- streamed pairs: 3 conflict-free LDS.128 per 2 pairs ----
#pragma unroll
        for (int h = 0; h < NCHUNK; ++h) {
            ulonglong2 xv = s->xb2[h][tid];
            ulonglong2 yv = s->yb2[h][tid];
            ulonglong2 zv = s->zb2[h][tid];
#pragma unroll
            for (int e = 0; e < 2; ++e) {
                const int j = REGJ + 2 * h + e;
                unsigned long long dx = fmx2(e ? xv.y : xv.x, ONE2, ncx);
                unsigned long long dy = fmx2(e ? yv.y : yv.x, ONE2, ncy);
                unsigned long long dz = fmx2(e ? zv.y : zv.x, ONE2, ncz);
                unsigned long long dd = fmx2(dx, dx, ZERO2);
                dd = fmx2(dy, dy, dd);
                dd = fmx2(dz, dz, dd);
                float d0, d1; unpackf2(dd, d0, d1);
                float m0 = fminf(m[2 * j],     d0);
                float m1 = fminf(m[2 * j + 1], d1);
                m[2 * j] = m0; m[2 * j + 1] = m1;
                bmA = fmaxf(bmA, m0);
                bmB = fmaxf(bmB, m1);
            }
        }
        const float bm = fmaxf(bmA, bmB);

        // ---- smallest k with m[k]==bm (downward scan) ----
        int kk = 0;
#pragma unroll
        for (int k = NPT - 1; k >= 0; --k)
            if (m[k] == bm) kk = k;

        const unsigned jw   = (unsigned)kk >> 1;
        const unsigned Pw   = jw * TPB + (unsigned)tid;
        const unsigned gidx = pbase + 2u * Pw + (unsigned)(kk & 1);

        unsigned long long wx, wy, wz;
        if (jw < REGJ) {
            wx = s->xa[Pw]; wy = s->ya[Pw]; wz = s->za[Pw];
        } else {
            int h = (int)(jw - REGJ) >> 1;
            if ((jw - REGJ) & 1) {
                wx = s->xb2[h][tid].y; wy = s->yb2[h][tid].y; wz = s->zb2[h][tid].y;
            } else {
                wx = s->xb2[h][tid].x; wy = s->yb2[h][tid].x; wz = s->zb2[h][tid].x;
            }
        }
        float a0, a1, b0, b1, c0, c1;
        unpackf2(wx, a0, a1);
        unpackf2(wy, b0, b1);
        unpackf2(wz, c0, c1);
        float candx = (kk & 1) ? a1 : a0;
        float candy = (kk & 1) ? b1 : b0;
        float candz = (kk & 1) ? c1 : c0;

        // ---- warp reduce: max dist bits, then min index among maxima ----
        unsigned vb = __float_as_uint(bm);   // d>=0: int order == float order
        unsigned wv = __reduce_max_sync(0xffffffffu, vb);
        unsigned cd = (vb == wv) ? gidx : 0xffffffffu;
        unsigned wi = __reduce_min_sync(0xffffffffu, cd);
        if (cd == wi) {                      // unique winner lane stores
            *reinterpret_cast<uint4*>(&s->warpred[warp]) =
                make_uint4(wv, wi, __float_as_uint(candx), __float_as_uint(candy));
            s->warpred[warp].z = candz;
        }
        __syncthreads();

        const int par = t & 1;

        // ---- block reduce over 16 warp partials + push to all 8 peers ----
        if (warp == 0) {
            unsigned v = 0, i = 0xffffffffu, xw = 0, yw = 0, zw = 0;
            if (lane < NWARPS) {
                uint4 w = *reinterpret_cast<const uint4*>(&s->warpred[lane]);
                v = w.x; i = w.y; xw = w.z; yw = w.w;
                zw = __float_as_uint(s->warpred[lane].z);
            }
            unsigned bv = __reduce_max_sync(0xffffffffu, v);
            unsigned bc = (v == bv) ? i : 0xffffffffu;
            unsigned bi = __reduce_min_sync(0xffffffffu, bc);
            unsigned msk = __ballot_sync(0xffffffffu, bc == bi);
            int L = __ffs(msk) - 1;
            xw = __shfl_sync(0xffffffffu, xw, L);
            yw = __shfl_sync(0xffffffffu, yw, L);
            zw = __shfl_sync(0xffffffffu, zw, L);
            if (lane < CSIZE) {
                unsigned ra = par ? rs1 : rs0;
                st_cluster_v4(ra, bv, bi, xw, yw);
                st_cluster_u32(ra + 16, zw);
            }
        }

        // one cluster barrier per step (arrive releases the DSMEM stores)
        cluster_bar();

        // ---- EVERY warp reduces the 8 slots -> next centroid in registers ----
        {
            unsigned v = 0, i = 0xffffffffu, xw = 0, yw = 0, zw = 0;
            if (lane < CSIZE) {
                uint4 w = *reinterpret_cast<const uint4*>(&s->slots[par][lane]);
                v = w.x; i = w.y; xw = w.z; yw = w.w;
                zw = __float_as_uint(s->slots[par][lane].z);
            }
            unsigned cv = __reduce_max_sync(0xffffffffu, v);
            unsigned cc = (v == cv) ? i : 0xffffffffu;
            unsigned ci = __reduce_min_sync(0xffffffffu, cc);
            unsigned msk = __ballot_sync(0xffffffffu, cc == ci);
            int W = __ffs(msk) - 1;
            cx = __uint_as_float(__shfl_sync(0xffffffffu, xw, W));
            cy = __uint_as_float(__shfl_sync(0xffffffffu, yw, W));
            cz = __uint_as_float(__shfl_sync(0xffffffffu, zw, W));
            if (rank == 0 && tid == 0) {
                float* o = out + ((size_t)batch * NSAMP + (size_t)t) * 3;
                o[0] = cx; o[1] = cy; o[2] = cz;
            }
        }
        // warpred: each warp rewrites only its own entry after its own warp
        // stage; warp0 reads right after the block-wide __syncthreads.
        // slots: double-buffered by parity, protected by the cluster barrier.
    }

    cluster_bar();  // keep CTAs alive until all DSMEM traffic has landed
}

extern "C" void kernel_launch(void* const* d_in, const int* in_sizes, int n_in,
                              void* d_out, int out_size) {
    (void)in_sizes; (void)n_in; (void)out_size;
    const float* xyz = (const float*)d_in[0];
    float* out = (float*)d_out;

    cudaFuncSetAttribute(fps_kernel,
                         cudaFuncAttributeMaxDynamicSharedMemorySize,
                         (int)sizeof(Smem));

    cudaLaunchConfig_t cfg = {};
    cfg.gridDim  = dim3(NB * CSIZE, 1, 1);   // 64 CTAs
    cfg.blockDim = dim3(TPB, 1, 1);
    cfg.dynamicSmemBytes = sizeof(Smem);
    cfg.stream = 0;

    cudaLaunchAttribute attr[1];
    attr[0].id = cudaLaunchAttributeClusterDimension;
    attr[0].val.clusterDim.x = CSIZE;
    attr[0].val.clusterDim.y = 1;
    attr[0].val.clusterDim.z = 1;
    cfg.attrs = attr;
    cfg.numAttrs = 1;

    cudaLaunchKernelEx(&cfg, fps_kernel, xyz, out);
}